// round 1
// baseline (speedup 1.0000x reference)
#include <cuda_runtime.h>

#define MDIM 81984   // B*V
#define VV   2562
#define HH   192
#define BB   32
#define CIN_K 966
#define PD_K  963

// ---------------- scratch (device globals; no allocations allowed) ----------
static __device__ float g_S[(size_t)MDIM * HH];   // GEMM output (support)
static __device__ float g_Yb[(size_t)MDIM * HH];  // pre-BN activation
static __device__ float g_X[(size_t)MDIM * HH];   // post-BN activation
static __device__ float g_F[(size_t)MDIM * HH];   // feats
static __device__ float g_S3[(size_t)MDIM * 3];   // head support
static __device__ float g_mean[VV];
static __device__ float g_var[VV];
static __device__ int   g_nbr[VV * 8];
static __device__ float g_w[VV * 8];
static __device__ int   g_cnt[VV];
static __device__ float g_invdeg[VV];

// ---------------- adjacency extraction: one warp per row --------------------
__global__ __launch_bounds__(256) void adj_kernel(const float* __restrict__ adj) {
    int u = blockIdx.x * (blockDim.x / 32) + (threadIdx.x / 32);
    int lane = threadIdx.x & 31;
    if (u >= VV) return;
    int cnt = 0;
    float deg = 0.f;
    for (int base = 0; base < VV; base += 32) {
        int v = base + lane;
        float f = (v < VV) ? adj[(size_t)u * VV + v] : 0.f;
        unsigned mask = __ballot_sync(0xffffffffu, f != 0.f);
        deg += f;
        if (f != 0.f) {
            int pos = cnt + __popc(mask & ((1u << lane) - 1u));
            if (pos < 8) { g_nbr[u * 8 + pos] = v; g_w[u * 8 + pos] = f; }
        }
        cnt += __popc(mask);
    }
    #pragma unroll
    for (int o = 16; o > 0; o >>= 1) deg += __shfl_down_sync(0xffffffffu, deg, o);
    if (lane == 0) {
        g_cnt[u] = cnt < 8 ? cnt : 8;
        g_invdeg[u] = 1.f / deg;
    }
}

// ---------------- fp32 tiled GEMM: C = A[M,K] * W[K,192] -> g_S --------------
// epilogue: columns < 64 scaled by invdeg[row % V] (side pre-normalization)
// CONCAT: A is virtual concat(features[M,3], pooled[M,963])
// src selects A buffer when !CONCAT: 0 -> g_X, 1 -> g_F
template<bool CONCAT>
__global__ __launch_bounds__(256) void gemm_kernel(
    const float* __restrict__ F3, const float* __restrict__ P,
    const float* __restrict__ W, int K, int src)
{
    __shared__ float As[16][128];
    __shared__ float Bs[16][64];
    const float* A = CONCAT ? nullptr : (src ? g_F : g_X);
    int t = threadIdx.x;
    int tx = t & 15;        // N direction (4 cols each)
    int ty = t >> 4;        // M direction (8 rows each)
    int rowBase = blockIdx.y * 128;
    int colBase = blockIdx.x * 64;
    float acc[8][4];
    #pragma unroll
    for (int i = 0; i < 8; i++)
        #pragma unroll
        for (int j = 0; j < 4; j++) acc[i][j] = 0.f;

    for (int k0 = 0; k0 < K; k0 += 16) {
        // load A tile 128x16 (8 elems/thread)
        #pragma unroll
        for (int i = 0; i < 8; i++) {
            int idx = t + i * 256;
            int r = idx >> 4, kk = idx & 15;
            int gm = rowBase + r, gk = k0 + kk;
            float v = 0.f;
            if (gm < MDIM && gk < K) {
                if (CONCAT) v = (gk < 3) ? F3[gm * 3 + gk] : P[(size_t)gm * PD_K + (gk - 3)];
                else        v = A[(size_t)gm * K + gk];
            }
            As[kk][r] = v;
        }
        // load B tile 16x64 (4 elems/thread)
        #pragma unroll
        for (int i = 0; i < 4; i++) {
            int idx = t + i * 256;
            int kk = idx >> 6, c = idx & 63;
            int gk = k0 + kk;
            Bs[kk][c] = (gk < K) ? W[(size_t)gk * HH + colBase + c] : 0.f;
        }
        __syncthreads();
        #pragma unroll
        for (int kk = 0; kk < 16; kk++) {
            float4 a0 = *reinterpret_cast<const float4*>(&As[kk][ty * 8]);
            float4 a1 = *reinterpret_cast<const float4*>(&As[kk][ty * 8 + 4]);
            float4 bv = *reinterpret_cast<const float4*>(&Bs[kk][tx * 4]);
            float a[8] = {a0.x, a0.y, a0.z, a0.w, a1.x, a1.y, a1.z, a1.w};
            float b[4] = {bv.x, bv.y, bv.z, bv.w};
            #pragma unroll
            for (int i = 0; i < 8; i++)
                #pragma unroll
                for (int j = 0; j < 4; j++) acc[i][j] = fmaf(a[i], b[j], acc[i][j]);
        }
        __syncthreads();
    }
    #pragma unroll
    for (int i = 0; i < 8; i++) {
        int gm = rowBase + ty * 8 + i;
        if (gm >= MDIM) continue;
        float inv = g_invdeg[gm % VV];
        #pragma unroll
        for (int j = 0; j < 4; j++) {
            int gc = colBase + tx * 4 + j;
            float v = acc[i][j];
            if (gc < 64) v *= inv;   // pre-normalize side channels
            g_S[(size_t)gm * HH + gc] = v;
        }
    }
}

// ---------------- combine: concat(support[64:], side) + bias ----------------
__global__ __launch_bounds__(192) void combine_kernel(const float* __restrict__ bias) {
    int m = blockIdx.x;
    int c = threadIdx.x;
    int v = m % VV, b = m / VV;
    float y;
    if (c < 128) {
        y = g_S[(size_t)m * HH + c + 64];
    } else {
        int d = c - 128;
        int cnt = g_cnt[v];
        float s = 0.f;
        for (int j = 0; j < cnt; j++) {
            int nv = g_nbr[v * 8 + j];
            s += g_w[v * 8 + j] * g_S[(size_t)(b * VV + nv) * HH + d];
        }
        y = s;
    }
    g_Yb[(size_t)m * HH + c] = y + bias[c];
}

// ---------------- BN stats per vertex over (B, C) ---------------------------
__global__ __launch_bounds__(256) void stats_kernel() {
    int v = blockIdx.x;
    int t = threadIdx.x;
    float s = 0.f, ss = 0.f;
    if (t < HH) {
        for (int b = 0; b < BB; b++) {
            float x = g_Yb[(size_t)(b * VV + v) * HH + t];
            s += x; ss += x * x;
        }
    }
    __shared__ float r1[256], r2[256];
    r1[t] = s; r2[t] = ss;
    __syncthreads();
    for (int o = 128; o > 0; o >>= 1) {
        if (t < o) { r1[t] += r1[t + o]; r2[t] += r2[t + o]; }
        __syncthreads();
    }
    if (t == 0) {
        float n = (float)(BB * HH);
        float mu = r1[0] / n;
        g_mean[v] = mu;
        g_var[v] = r2[0] / n - mu * mu;
    }
}

// ---------------- BN apply + ReLU (+ residual variants) ---------------------
// mode 0: g_X = relu(bn)
// mode 1: g_F = (concat_input_first192 + relu(bn)) / 2
// mode 2: g_F = (g_F + relu(bn)) / 2
// mode 3: mode 2, also write d_out feats region
__global__ __launch_bounds__(256) void apply_kernel(
    const float* __restrict__ gam, const float* __restrict__ bet,
    const float* __restrict__ F3, const float* __restrict__ P,
    float* __restrict__ dout, int mode)
{
    size_t idx = (size_t)blockIdx.x * blockDim.x + threadIdx.x;
    if (idx >= (size_t)MDIM * HH) return;
    int m = (int)(idx / HH), c = (int)(idx % HH);
    int v = m % VV;
    float mu = g_mean[v], va = g_var[v];
    float y = gam[v] * (g_Yb[idx] - mu) * rsqrtf(va + 1e-5f) + bet[v];
    y = fmaxf(y, 0.f);
    if (mode == 0) {
        g_X[idx] = y;
    } else if (mode == 1) {
        float base = (c < 3) ? F3[m * 3 + c] : P[(size_t)m * PD_K + (c - 3)];
        g_F[idx] = (base + y) * 0.5f;
    } else {
        float r = (g_F[idx] + y) * 0.5f;
        g_F[idx] = r;
        if (mode == 3) dout[idx] = r;
    }
}

// ---------------- head GEMM: S3 = feats @ W15 [M,3], cols<2 pre-scaled ------
__global__ __launch_bounds__(256) void gemm3_kernel(const float* __restrict__ W15) {
    int warp = (blockIdx.x * blockDim.x + threadIdx.x) >> 5;
    int lane = threadIdx.x & 31;
    if (warp >= MDIM) return;
    const float* row = g_F + (size_t)warp * HH;
    float a0 = 0.f, a1 = 0.f, a2 = 0.f;
    for (int k = lane; k < HH; k += 32) {
        float f = row[k];
        a0 = fmaf(f, W15[k * 3 + 0], a0);
        a1 = fmaf(f, W15[k * 3 + 1], a1);
        a2 = fmaf(f, W15[k * 3 + 2], a2);
    }
    #pragma unroll
    for (int o = 16; o > 0; o >>= 1) {
        a0 += __shfl_down_sync(0xffffffffu, a0, o);
        a1 += __shfl_down_sync(0xffffffffu, a1, o);
        a2 += __shfl_down_sync(0xffffffffu, a2, o);
    }
    if (lane == 0) {
        float inv = g_invdeg[warp % VV];
        g_S3[warp * 3 + 0] = a0 * inv;  // side channels pre-normalized
        g_S3[warp * 3 + 1] = a1 * inv;
        g_S3[warp * 3 + 2] = a2;
    }
}

// ---------------- coords: concat(support[2:3], side[0:2]) + b15 -------------
__global__ __launch_bounds__(256) void coords_kernel(float* __restrict__ dout,
                                                     const float* __restrict__ b15) {
    int m = blockIdx.x * blockDim.x + threadIdx.x;
    if (m >= MDIM) return;
    int v = m % VV, b = m / VV;
    float s0 = 0.f, s1 = 0.f;
    int cnt = g_cnt[v];
    for (int j = 0; j < cnt; j++) {
        int nv = g_nbr[v * 8 + j];
        float w = g_w[v * 8 + j];
        const float* p = g_S3 + (size_t)(b * VV + nv) * 3;
        s0 += w * p[0];
        s1 += w * p[1];
    }
    float* o = dout + (size_t)MDIM * HH + (size_t)m * 3;
    o[0] = g_S3[m * 3 + 2] + b15[0];
    o[1] = s0 + b15[1];
    o[2] = s1 + b15[2];
}

// ---------------- driver ----------------------------------------------------
extern "C" void kernel_launch(void* const* d_in, const int* in_sizes, int n_in,
                              void* d_out, int out_size) {
    const float* features = (const float*)d_in[0];  // [B,V,3]
    const float* pooled   = (const float*)d_in[1];  // [B,V,963]
    const float* adj      = (const float*)d_in[2];  // [V,V]
    const float* W1       = (const float*)d_in[3];  // [966,192]
    const float* b1       = (const float*)d_in[4];  // [192]
    const float* Wm       = (const float*)d_in[5];  // [12,192,192]
    const float* bm       = (const float*)d_in[6];  // [12,192]
    const float* W15      = (const float*)d_in[7];  // [192,3]
    const float* b15      = (const float*)d_in[8];  // [3]
    const float* gamma    = (const float*)d_in[9];  // [13,V]
    const float* beta     = (const float*)d_in[10]; // [13,V]
    float* dout = (float*)d_out;

    dim3 ggrid(3, (MDIM + 127) / 128);
    int apply_grid = (int)(((size_t)MDIM * HH + 255) / 256);

    adj_kernel<<<(VV + 7) / 8, 256>>>(adj);

    // layer 1: concat input, K=966 -> g_X (mode 0), bn row 0
    gemm_kernel<true><<<ggrid, 256>>>(features, pooled, W1, CIN_K, 0);
    combine_kernel<<<MDIM, 192>>>(b1);
    stats_kernel<<<VV, 256>>>();
    apply_kernel<<<apply_grid, 256>>>(gamma + 0 * VV, beta + 0 * VV, features, pooled, dout, 0);

    // layer 2: Wm[0], input g_X -> feats = (full192 + x)/2 (mode 1), bn row 1
    gemm_kernel<false><<<ggrid, 256>>>(nullptr, nullptr, Wm + (size_t)0 * HH * HH, HH, 0);
    combine_kernel<<<MDIM, 192>>>(bm + 0 * HH);
    stats_kernel<<<VV, 256>>>();
    apply_kernel<<<apply_grid, 256>>>(gamma + 1 * VV, beta + 1 * VV, features, pooled, dout, 1);

    // 5 residual pairs
    for (int i = 0; i < 5; i++) {
        int wa = 2 * i + 1, wb = 2 * i + 2;
        // first of pair: input g_F -> g_X (mode 0), bn row 2i+2
        gemm_kernel<false><<<ggrid, 256>>>(nullptr, nullptr, Wm + (size_t)wa * HH * HH, HH, 1);
        combine_kernel<<<MDIM, 192>>>(bm + wa * HH);
        stats_kernel<<<VV, 256>>>();
        apply_kernel<<<apply_grid, 256>>>(gamma + (2 * i + 2) * VV, beta + (2 * i + 2) * VV,
                                          features, pooled, dout, 0);
        // second of pair: input g_X -> feats update (mode 2), bn row 2i+3
        gemm_kernel<false><<<ggrid, 256>>>(nullptr, nullptr, Wm + (size_t)wb * HH * HH, HH, 0);
        combine_kernel<<<MDIM, 192>>>(bm + wb * HH);
        stats_kernel<<<VV, 256>>>();
        apply_kernel<<<apply_grid, 256>>>(gamma + (2 * i + 3) * VV, beta + (2 * i + 3) * VV,
                                          features, pooled, dout, 2);
    }

    // layer 13: Wm[11], input g_F -> feats update + write d_out (mode 3), bn row 12
    gemm_kernel<false><<<ggrid, 256>>>(nullptr, nullptr, Wm + (size_t)11 * HH * HH, HH, 1);
    combine_kernel<<<MDIM, 192>>>(bm + 11 * HH);
    stats_kernel<<<VV, 256>>>();
    apply_kernel<<<apply_grid, 256>>>(gamma + 12 * VV, beta + 12 * VV, features, pooled, dout, 3);

    // head: coords
    gemm3_kernel<<<(MDIM * 32 + 255) / 256, 256>>>(W15);
    coords_kernel<<<(MDIM + 255) / 256, 256>>>(dout, b15);
}

// round 2
// speedup vs baseline: 1.5080x; 1.5080x over previous
#include <cuda_runtime.h>
#include <cstdint>

#define MDIM 81984   // B*V
#define VV   2562
#define HH   192
#define BB   32
#define CIN_K 966
#define PD_K  963

// ---------------- scratch (device globals; no allocations allowed) ----------
static __device__ float g_S[(size_t)MDIM * HH];   // GEMM output (support, side pre-scaled)
static __device__ float g_X[(size_t)MDIM * HH];   // post-BN activation
static __device__ float g_F[(size_t)MDIM * HH];   // feats
static __device__ float g_S3[(size_t)MDIM * 3];   // head support
static __device__ int   g_nbr[VV * 8];
static __device__ float g_w[VV * 8];
static __device__ int   g_cnt[VV];
static __device__ float g_invdeg[VV];

// ---------------- adjacency extraction: one warp per row --------------------
__global__ __launch_bounds__(256) void adj_kernel(const float* __restrict__ adj) {
    int u = blockIdx.x * (blockDim.x / 32) + (threadIdx.x / 32);
    int lane = threadIdx.x & 31;
    if (u >= VV) return;
    int cnt = 0;
    float deg = 0.f;
    for (int base = 0; base < VV; base += 32) {
        int v = base + lane;
        float f = (v < VV) ? adj[(size_t)u * VV + v] : 0.f;
        unsigned mask = __ballot_sync(0xffffffffu, f != 0.f);
        deg += f;
        if (f != 0.f) {
            int pos = cnt + __popc(mask & ((1u << lane) - 1u));
            if (pos < 8) { g_nbr[u * 8 + pos] = v; g_w[u * 8 + pos] = f; }
        }
        cnt += __popc(mask);
    }
    #pragma unroll
    for (int o = 16; o > 0; o >>= 1) deg += __shfl_down_sync(0xffffffffu, deg, o);
    if (lane == 0) {
        g_cnt[u] = cnt < 8 ? cnt : 8;
        g_invdeg[u] = 1.f / deg;
    }
}

// ---------------- tf32 helpers ----------------------------------------------
__device__ __forceinline__ void tf32_split(float x, uint32_t& hi, uint32_t& lo) {
    uint32_t h;
    asm("cvt.rna.tf32.f32 %0, %1;" : "=r"(h) : "f"(x));
    float r = x - __uint_as_float(h);
    uint32_t l;
    asm("cvt.rna.tf32.f32 %0, %1;" : "=r"(l) : "f"(r));
    hi = h; lo = l;
}

__device__ __forceinline__ void mma8(float* c, const uint32_t* a, const uint32_t* b) {
    asm volatile(
        "mma.sync.aligned.m16n8k8.row.col.f32.tf32.tf32.f32 "
        "{%0,%1,%2,%3}, {%4,%5,%6,%7}, {%8,%9}, {%0,%1,%2,%3};\n"
        : "+f"(c[0]), "+f"(c[1]), "+f"(c[2]), "+f"(c[3])
        : "r"(a[0]), "r"(a[1]), "r"(a[2]), "r"(a[3]), "r"(b[0]), "r"(b[1]));
}

// ---------------- 3xTF32 tensor-core GEMM: g_S = A[M,K] * W[K,192] ----------
// epilogue: cols < 64 scaled by invdeg[row % V]
// CONCAT: A = concat(features[M,3], pooled[M,963]); else A = (src ? g_F : g_X)
template<bool CONCAT>
__global__ __launch_bounds__(256) void gemm_tf32_kernel(
    const float* __restrict__ F3, const float* __restrict__ P,
    const float* __restrict__ W, int K, int src)
{
    __shared__ float As[128][20];   // [m][k], pad 4
    __shared__ float Bs[16][68];    // [k][n], pad 4
    const float* A = CONCAT ? nullptr : (src ? g_F : g_X);
    int t = threadIdx.x;
    int lane = t & 31, warp = t >> 5;
    int wm = (warp >> 1) * 32, wn = (warp & 1) * 32;
    int g = lane >> 2, t4 = lane & 3;
    int rowBase = blockIdx.y * 128, colBase = blockIdx.x * 64;

    float acc[2][4][4];
    #pragma unroll
    for (int mt = 0; mt < 2; mt++)
        #pragma unroll
        for (int nt = 0; nt < 4; nt++)
            #pragma unroll
            for (int i = 0; i < 4; i++) acc[mt][nt][i] = 0.f;

    for (int k0 = 0; k0 < K; k0 += 16) {
        // ---- load A tile 128x16 ----
        if (CONCAT) {
            #pragma unroll
            for (int i = 0; i < 8; i++) {
                int idx = t + i * 256;
                int r = idx >> 4, kk = idx & 15;
                int gm = rowBase + r, gk = k0 + kk;
                float v = 0.f;
                if (gm < MDIM && gk < K)
                    v = (gk < 3) ? F3[gm * 3 + gk] : P[(size_t)gm * PD_K + (gk - 3)];
                As[r][kk] = v;
            }
        } else {
            int r = t >> 1, kk8 = (t & 1) * 8;
            int gm = rowBase + r;
            float4 v0 = make_float4(0.f, 0.f, 0.f, 0.f), v1 = v0;
            if (gm < MDIM) {
                const float4* src4 = reinterpret_cast<const float4*>(A + (size_t)gm * HH + k0 + kk8);
                v0 = src4[0]; v1 = src4[1];
            }
            *reinterpret_cast<float4*>(&As[r][kk8])     = v0;
            *reinterpret_cast<float4*>(&As[r][kk8 + 4]) = v1;
        }
        // ---- load B tile 16x64 ----
        {
            int r = t >> 4, c4 = (t & 15) * 4;
            int gk = k0 + r;
            float4 v = make_float4(0.f, 0.f, 0.f, 0.f);
            if (gk < K)
                v = *reinterpret_cast<const float4*>(W + (size_t)gk * HH + colBase + c4);
            *reinterpret_cast<float4*>(&Bs[r][c4]) = v;
        }
        __syncthreads();

        #pragma unroll
        for (int ks = 0; ks < 2; ks++) {
            int kk = ks * 8;
            uint32_t ah[2][4], al[2][4];
            #pragma unroll
            for (int mt = 0; mt < 2; mt++) {
                int rm = wm + mt * 16 + g;
                tf32_split(As[rm][kk + t4],          ah[mt][0], al[mt][0]);
                tf32_split(As[rm + 8][kk + t4],      ah[mt][1], al[mt][1]);
                tf32_split(As[rm][kk + t4 + 4],      ah[mt][2], al[mt][2]);
                tf32_split(As[rm + 8][kk + t4 + 4],  ah[mt][3], al[mt][3]);
            }
            uint32_t bh[4][2], bl[4][2];
            #pragma unroll
            for (int nt = 0; nt < 4; nt++) {
                int cn = wn + nt * 8 + g;
                tf32_split(Bs[kk + t4][cn],     bh[nt][0], bl[nt][0]);
                tf32_split(Bs[kk + t4 + 4][cn], bh[nt][1], bl[nt][1]);
            }
            #pragma unroll
            for (int mt = 0; mt < 2; mt++)
                #pragma unroll
                for (int nt = 0; nt < 4; nt++) {
                    mma8(acc[mt][nt], ah[mt], bh[nt]);
                    mma8(acc[mt][nt], al[mt], bh[nt]);
                    mma8(acc[mt][nt], ah[mt], bl[nt]);
                }
        }
        __syncthreads();
    }

    // ---- epilogue ----
    #pragma unroll
    for (int mt = 0; mt < 2; mt++) {
        int gm0 = rowBase + wm + mt * 16 + g;
        #pragma unroll
        for (int nt = 0; nt < 4; nt++) {
            int gc = colBase + wn + nt * 8 + t4 * 2;
            bool side = (gc < 64);
            if (gm0 < MDIM) {
                float sc = side ? g_invdeg[gm0 % VV] : 1.f;
                float2 v = make_float2(acc[mt][nt][0] * sc, acc[mt][nt][1] * sc);
                *reinterpret_cast<float2*>(&g_S[(size_t)gm0 * HH + gc]) = v;
            }
            int gm1 = gm0 + 8;
            if (gm1 < MDIM) {
                float sc = side ? g_invdeg[gm1 % VV] : 1.f;
                float2 v = make_float2(acc[mt][nt][2] * sc, acc[mt][nt][3] * sc);
                *reinterpret_cast<float2*>(&g_S[(size_t)gm1 * HH + gc]) = v;
            }
        }
    }
}

// ---------------- fused combine + BN stats + BN apply (per vertex) ----------
// mode 0: g_X = relu(bn)
// mode 1: g_F = (concat_first192 + relu(bn)) / 2
// mode 2: g_F = (g_F + relu(bn)) / 2
// mode 3: mode 2 + write dout
__global__ __launch_bounds__(256) void post_kernel(
    const float* __restrict__ bias,
    const float* __restrict__ gam, const float* __restrict__ bet,
    const float* __restrict__ F3, const float* __restrict__ P,
    float* __restrict__ dout, int mode)
{
    int v = blockIdx.x, t = threadIdx.x;
    __shared__ float ybuf[BB * HH];            // 6144 floats = 24KB
    __shared__ int   s_nbr[8];
    __shared__ float s_w[8];
    __shared__ int   s_cnt;
    __shared__ float redS[8], redQ[8];
    __shared__ float s_mean, s_istd;

    if (t < 8) { s_nbr[t] = g_nbr[v * 8 + t]; s_w[t] = g_w[v * 8 + t]; }
    if (t == 0) s_cnt = g_cnt[v];
    __syncthreads();
    int cnt = s_cnt;

    float s = 0.f, ss = 0.f;
    #pragma unroll
    for (int it = 0; it < 24; it++) {
        int i = t + it * 256;
        int b = i / HH, c = i - b * HH;
        float y;
        if (c < 128) {
            y = g_S[((size_t)(b * VV + v)) * HH + c + 64];
        } else {
            int d = c - 128;
            y = 0.f;
            for (int j = 0; j < cnt; j++)
                y += s_w[j] * g_S[((size_t)(b * VV + s_nbr[j])) * HH + d];
        }
        y += bias[c];
        ybuf[i] = y;
        s += y; ss += y * y;
    }
    // reduce over block
    #pragma unroll
    for (int o = 16; o > 0; o >>= 1) {
        s  += __shfl_down_sync(0xffffffffu, s, o);
        ss += __shfl_down_sync(0xffffffffu, ss, o);
    }
    int lane = t & 31, warp = t >> 5;
    if (lane == 0) { redS[warp] = s; redQ[warp] = ss; }
    __syncthreads();
    if (t == 0) {
        float S = 0.f, Q = 0.f;
        #pragma unroll
        for (int w = 0; w < 8; w++) { S += redS[w]; Q += redQ[w]; }
        float n = (float)(BB * HH);
        float mu = S / n;
        float var = Q / n - mu * mu;
        s_mean = mu;
        s_istd = rsqrtf(var + 1e-5f);
    }
    __syncthreads();

    float gv = gam[v], bv = bet[v], mu = s_mean, istd = s_istd;
    #pragma unroll
    for (int it = 0; it < 24; it++) {
        int i = t + it * 256;
        int b = i / HH, c = i - b * HH;
        float y = gv * (ybuf[i] - mu) * istd + bv;
        y = fmaxf(y, 0.f);
        size_t o = ((size_t)(b * VV + v)) * HH + c;
        if (mode == 0) {
            g_X[o] = y;
        } else if (mode == 1) {
            int m = b * VV + v;
            float base = (c < 3) ? F3[m * 3 + c] : P[(size_t)m * PD_K + (c - 3)];
            g_F[o] = (base + y) * 0.5f;
        } else {
            float r = (g_F[o] + y) * 0.5f;
            g_F[o] = r;
            if (mode == 3) dout[o] = r;
        }
    }
}

// ---------------- head GEMM: S3 = feats @ W15 [M,3], cols<2 pre-scaled ------
__global__ __launch_bounds__(256) void gemm3_kernel(const float* __restrict__ W15) {
    int warp = (blockIdx.x * blockDim.x + threadIdx.x) >> 5;
    int lane = threadIdx.x & 31;
    if (warp >= MDIM) return;
    const float* row = g_F + (size_t)warp * HH;
    float a0 = 0.f, a1 = 0.f, a2 = 0.f;
    for (int k = lane; k < HH; k += 32) {
        float f = row[k];
        a0 = fmaf(f, W15[k * 3 + 0], a0);
        a1 = fmaf(f, W15[k * 3 + 1], a1);
        a2 = fmaf(f, W15[k * 3 + 2], a2);
    }
    #pragma unroll
    for (int o = 16; o > 0; o >>= 1) {
        a0 += __shfl_down_sync(0xffffffffu, a0, o);
        a1 += __shfl_down_sync(0xffffffffu, a1, o);
        a2 += __shfl_down_sync(0xffffffffu, a2, o);
    }
    if (lane == 0) {
        float inv = g_invdeg[warp % VV];
        g_S3[warp * 3 + 0] = a0 * inv;
        g_S3[warp * 3 + 1] = a1 * inv;
        g_S3[warp * 3 + 2] = a2;
    }
}

// ---------------- coords: concat(support[2:3], side[0:2]) + b15 -------------
__global__ __launch_bounds__(256) void coords_kernel(float* __restrict__ dout,
                                                     const float* __restrict__ b15) {
    int m = blockIdx.x * blockDim.x + threadIdx.x;
    if (m >= MDIM) return;
    int v = m % VV, b = m / VV;
    float s0 = 0.f, s1 = 0.f;
    int cnt = g_cnt[v];
    for (int j = 0; j < cnt; j++) {
        int nv = g_nbr[v * 8 + j];
        float w = g_w[v * 8 + j];
        const float* p = g_S3 + (size_t)(b * VV + nv) * 3;
        s0 += w * p[0];
        s1 += w * p[1];
    }
    float* o = dout + (size_t)MDIM * HH + (size_t)m * 3;
    o[0] = g_S3[m * 3 + 2] + b15[0];
    o[1] = s0 + b15[1];
    o[2] = s1 + b15[2];
}

// ---------------- driver ----------------------------------------------------
extern "C" void kernel_launch(void* const* d_in, const int* in_sizes, int n_in,
                              void* d_out, int out_size) {
    const float* features = (const float*)d_in[0];
    const float* pooled   = (const float*)d_in[1];
    const float* adj      = (const float*)d_in[2];
    const float* W1       = (const float*)d_in[3];
    const float* b1       = (const float*)d_in[4];
    const float* Wm       = (const float*)d_in[5];
    const float* bm       = (const float*)d_in[6];
    const float* W15      = (const float*)d_in[7];
    const float* b15      = (const float*)d_in[8];
    const float* gamma    = (const float*)d_in[9];
    const float* beta     = (const float*)d_in[10];
    float* dout = (float*)d_out;

    dim3 ggrid(3, (MDIM + 127) / 128);

    adj_kernel<<<(VV + 7) / 8, 256>>>(adj);

    // layer 1
    gemm_tf32_kernel<true><<<ggrid, 256>>>(features, pooled, W1, CIN_K, 0);
    post_kernel<<<VV, 256>>>(b1, gamma + 0 * VV, beta + 0 * VV, features, pooled, dout, 0);

    // layer 2
    gemm_tf32_kernel<false><<<ggrid, 256>>>(nullptr, nullptr, Wm + (size_t)0 * HH * HH, HH, 0);
    post_kernel<<<VV, 256>>>(bm + 0 * HH, gamma + 1 * VV, beta + 1 * VV, features, pooled, dout, 1);

    // 5 residual pairs
    for (int i = 0; i < 5; i++) {
        int wa = 2 * i + 1, wb = 2 * i + 2;
        gemm_tf32_kernel<false><<<ggrid, 256>>>(nullptr, nullptr, Wm + (size_t)wa * HH * HH, HH, 1);
        post_kernel<<<VV, 256>>>(bm + wa * HH, gamma + (2 * i + 2) * VV, beta + (2 * i + 2) * VV,
                                 features, pooled, dout, 0);
        gemm_tf32_kernel<false><<<ggrid, 256>>>(nullptr, nullptr, Wm + (size_t)wb * HH * HH, HH, 0);
        post_kernel<<<VV, 256>>>(bm + wb * HH, gamma + (2 * i + 3) * VV, beta + (2 * i + 3) * VV,
                                 features, pooled, dout, 2);
    }

    // layer 13
    gemm_tf32_kernel<false><<<ggrid, 256>>>(nullptr, nullptr, Wm + (size_t)11 * HH * HH, HH, 1);
    post_kernel<<<VV, 256>>>(bm + 11 * HH, gamma + 12 * VV, beta + 12 * VV, features, pooled, dout, 3);

    // head
    gemm3_kernel<<<(MDIM * 32 + 255) / 256, 256>>>(W15);
    coords_kernel<<<(MDIM + 255) / 256, 256>>>(dout, b15);
}

// round 3
// speedup vs baseline: 2.6851x; 1.7806x over previous
#include <cuda_runtime.h>
#include <cuda_bf16.h>
#include <cstdint>

#define MDIM 81984   // B*V
#define VV   2562
#define HH   192
#define BB   32
#define KP_H 96      // k-pairs for K=192
#define KP_1 488     // k-pairs for layer1 (K=966 padded to 976)
#define NT_H 12
#define NT_1 61
#define WROWS (KP_1 + 12 * KP_H)

// ---------------- scratch (device globals) ----------------------------------
static __device__ float    g_S [(size_t)MDIM * HH];      // GEMM out (side pre-scaled)
static __device__ float    g_F [(size_t)MDIM * HH];      // feats fp32
static __device__ uint32_t g_Xh[(size_t)MDIM * KP_H];    // X bf16 hi plane (packed pairs)
static __device__ uint32_t g_Xl[(size_t)MDIM * KP_H];
static __device__ uint32_t g_Fh[(size_t)MDIM * KP_H];
static __device__ uint32_t g_Fl[(size_t)MDIM * KP_H];
static __device__ uint32_t g_A1h[(size_t)MDIM * KP_1];   // layer1 concat input planes
static __device__ uint32_t g_A1l[(size_t)MDIM * KP_1];
static __device__ uint32_t g_Wh[(size_t)WROWS * HH];     // weights planes [kpair][n]
static __device__ uint32_t g_Wl[(size_t)WROWS * HH];
static __device__ float    g_S3[(size_t)MDIM * 3];
static __device__ int      g_nbr[VV * 8];
static __device__ float    g_w [VV * 8];
static __device__ int      g_cnt[VV];
static __device__ float    g_invdeg[VV];

// ---------------- helpers ----------------------------------------------------
__device__ __forceinline__ void split2(float x0, float x1, uint32_t& hi, uint32_t& lo) {
    __nv_bfloat16 h0 = __float2bfloat16(x0);
    __nv_bfloat16 h1 = __float2bfloat16(x1);
    __nv_bfloat16 l0 = __float2bfloat16(x0 - __bfloat162float(h0));
    __nv_bfloat16 l1 = __float2bfloat16(x1 - __bfloat162float(h1));
    hi = (uint32_t)__bfloat16_as_ushort(h0) | ((uint32_t)__bfloat16_as_ushort(h1) << 16);
    lo = (uint32_t)__bfloat16_as_ushort(l0) | ((uint32_t)__bfloat16_as_ushort(l1) << 16);
}

__device__ __forceinline__ void mma16(float* c, const uint32_t* a, const uint32_t* b) {
    asm volatile(
        "mma.sync.aligned.m16n8k16.row.col.f32.bf16.bf16.f32 "
        "{%0,%1,%2,%3}, {%4,%5,%6,%7}, {%8,%9}, {%0,%1,%2,%3};\n"
        : "+f"(c[0]), "+f"(c[1]), "+f"(c[2]), "+f"(c[3])
        : "r"(a[0]), "r"(a[1]), "r"(a[2]), "r"(a[3]), "r"(b[0]), "r"(b[1]));
}

// ---------------- adjacency extraction ---------------------------------------
__global__ __launch_bounds__(256) void adj_kernel(const float* __restrict__ adj) {
    int u = blockIdx.x * (blockDim.x / 32) + (threadIdx.x / 32);
    int lane = threadIdx.x & 31;
    if (u >= VV) return;
    int cnt = 0;
    float deg = 0.f;
    for (int base = 0; base < VV; base += 32) {
        int v = base + lane;
        float f = (v < VV) ? adj[(size_t)u * VV + v] : 0.f;
        unsigned mask = __ballot_sync(0xffffffffu, f != 0.f);
        deg += f;
        if (f != 0.f) {
            int pos = cnt + __popc(mask & ((1u << lane) - 1u));
            if (pos < 8) { g_nbr[u * 8 + pos] = v; g_w[u * 8 + pos] = f; }
        }
        cnt += __popc(mask);
    }
    #pragma unroll
    for (int o = 16; o > 0; o >>= 1) deg += __shfl_down_sync(0xffffffffu, deg, o);
    if (lane == 0) {
        g_cnt[u] = cnt < 8 ? cnt : 8;
        g_invdeg[u] = 1.f / deg;
    }
}

// ---------------- weight pre-split: W1 + Wm -> g_Wh/g_Wl --------------------
__global__ __launch_bounds__(256) void prep_w_kernel(const float* __restrict__ W1,
                                                     const float* __restrict__ Wm) {
    int idx = blockIdx.x * 256 + threadIdx.x;
    if (idx >= WROWS * HH) return;
    int kp = idx / HH, n = idx % HH;
    float x0, x1;
    if (kp < KP_1) {
        int k = 2 * kp;
        x0 = (k < 966)     ? W1[(size_t)k * HH + n]       : 0.f;
        x1 = (k + 1 < 966) ? W1[(size_t)(k + 1) * HH + n] : 0.f;
    } else {
        int r = kp - KP_1;
        int mat = r / KP_H, kpp = r % KP_H;
        int k = 2 * kpp;
        const float* Wb = Wm + (size_t)mat * HH * HH;
        x0 = Wb[(size_t)k * HH + n];
        x1 = Wb[(size_t)(k + 1) * HH + n];
    }
    split2(x0, x1, g_Wh[idx], g_Wl[idx]);
}

// ---------------- layer1 input pre-split: concat(F3,P) -> g_A1h/l -----------
__global__ __launch_bounds__(256) void prep_a1_kernel(const float* __restrict__ F3,
                                                      const float* __restrict__ P) {
    size_t idx = (size_t)blockIdx.x * 256 + threadIdx.x;
    if (idx >= (size_t)MDIM * KP_1) return;
    int m = (int)(idx / KP_1), kp = (int)(idx % KP_1);
    int c = 2 * kp;
    float x0 = 0.f, x1 = 0.f;
    if (c < 3)        x0 = F3[m * 3 + c];
    else if (c < 966) x0 = P[(size_t)m * 963 + (c - 3)];
    int c1 = c + 1;
    if (c1 < 3)        x1 = F3[m * 3 + c1];
    else if (c1 < 966) x1 = P[(size_t)m * 963 + (c1 - 3)];
    split2(x0, x1, g_A1h[idx], g_A1l[idx]);
}

// ---------------- bf16x3 tensor-core GEMM: g_S = A[M,K] @ W[K,192] -----------
// epilogue: cols < 64 scaled by invdeg[row % V]
// asel: 0 -> g_Xh/l (akp=96), 1 -> g_Fh/l (96), 2 -> g_A1h/l (488)
__global__ __launch_bounds__(256) void gemm_bf3_kernel(int asel, int woff, int NT) {
    __shared__ uint32_t Ash[128][12], Asl[128][12];
    __shared__ uint32_t Bsh[8][72],  Bsl[8][72];

    const uint32_t* Ah; const uint32_t* Al; int akp;
    if (asel == 0)      { Ah = g_Xh;  Al = g_Xl;  akp = KP_H; }
    else if (asel == 1) { Ah = g_Fh;  Al = g_Fl;  akp = KP_H; }
    else                { Ah = g_A1h; Al = g_A1l; akp = KP_1; }
    const uint32_t* Bh = g_Wh + (size_t)woff * HH;
    const uint32_t* Bl = g_Wl + (size_t)woff * HH;

    int t = threadIdx.x, lane = t & 31, warp = t >> 5;
    int wm = (warp >> 1) * 32, wn = (warp & 1) * 32;
    int g = lane >> 2, t4 = lane & 3;
    int rowBase = blockIdx.y * 128, colBase = blockIdx.x * 64;

    float acc[2][4][4];
    #pragma unroll
    for (int mt = 0; mt < 2; mt++)
        #pragma unroll
        for (int nt = 0; nt < 4; nt++)
            #pragma unroll
            for (int i = 0; i < 4; i++) acc[mt][nt][i] = 0.f;

    int ar = t >> 1, akp4 = (t & 1) * 4;       // A loader: row, kpair quad
    int bn = t & 63, bk = t >> 6;              // B loader: col, kpair row
    int gmA = rowBase + ar;

    uint4 pAh, pAl;
    uint32_t pBh0, pBh1, pBl0, pBl1;

    auto ldtile = [&](int kt) {
        int k0p = kt * 8;
        if (gmA < MDIM) {
            pAh = *(const uint4*)(Ah + (size_t)gmA * akp + k0p + akp4);
            pAl = *(const uint4*)(Al + (size_t)gmA * akp + k0p + akp4);
        } else {
            pAh = make_uint4(0u, 0u, 0u, 0u);
            pAl = make_uint4(0u, 0u, 0u, 0u);
        }
        size_t b0 = (size_t)(k0p + bk) * HH + colBase + bn;
        size_t b1 = (size_t)(k0p + bk + 4) * HH + colBase + bn;
        pBh0 = Bh[b0]; pBh1 = Bh[b1];
        pBl0 = Bl[b0]; pBl1 = Bl[b1];
    };

    ldtile(0);
    for (int kt = 0; kt < NT; kt++) {
        __syncthreads();
        *(uint4*)&Ash[ar][akp4] = pAh;
        *(uint4*)&Asl[ar][akp4] = pAl;
        Bsh[bk][bn] = pBh0; Bsh[bk + 4][bn] = pBh1;
        Bsl[bk][bn] = pBl0; Bsl[bk + 4][bn] = pBl1;
        __syncthreads();
        if (kt + 1 < NT) ldtile(kt + 1);

        uint32_t ah[2][4], al[2][4];
        #pragma unroll
        for (int mt = 0; mt < 2; mt++) {
            int rm = wm + mt * 16 + g;
            ah[mt][0] = Ash[rm][t4];     ah[mt][1] = Ash[rm + 8][t4];
            ah[mt][2] = Ash[rm][t4 + 4]; ah[mt][3] = Ash[rm + 8][t4 + 4];
            al[mt][0] = Asl[rm][t4];     al[mt][1] = Asl[rm + 8][t4];
            al[mt][2] = Asl[rm][t4 + 4]; al[mt][3] = Asl[rm + 8][t4 + 4];
        }
        #pragma unroll
        for (int nt = 0; nt < 4; nt++) {
            int cn = wn + nt * 8 + g;
            uint32_t bh[2] = { Bsh[t4][cn], Bsh[t4 + 4][cn] };
            uint32_t bl[2] = { Bsl[t4][cn], Bsl[t4 + 4][cn] };
            #pragma unroll
            for (int mt = 0; mt < 2; mt++) {
                mma16(acc[mt][nt], ah[mt], bh);
                mma16(acc[mt][nt], al[mt], bh);
                mma16(acc[mt][nt], ah[mt], bl);
            }
        }
    }

    #pragma unroll
    for (int mt = 0; mt < 2; mt++) {
        int gm0 = rowBase + wm + mt * 16 + g;
        #pragma unroll
        for (int nt = 0; nt < 4; nt++) {
            int gc = colBase + wn + nt * 8 + t4 * 2;
            bool side = (gc < 64);
            if (gm0 < MDIM) {
                float sc = side ? g_invdeg[gm0 % VV] : 1.f;
                *reinterpret_cast<float2*>(&g_S[(size_t)gm0 * HH + gc]) =
                    make_float2(acc[mt][nt][0] * sc, acc[mt][nt][1] * sc);
            }
            int gm1 = gm0 + 8;
            if (gm1 < MDIM) {
                float sc = side ? g_invdeg[gm1 % VV] : 1.f;
                *reinterpret_cast<float2*>(&g_S[(size_t)gm1 * HH + gc]) =
                    make_float2(acc[mt][nt][2] * sc, acc[mt][nt][3] * sc);
            }
        }
    }
}

// ---------------- fused combine + BN stats + apply (per vertex) --------------
// mode 0: X = relu(bn)                (write g_Xh/l planes only)
// mode 1: F = (concat_first192+y)/2   (write g_F + planes)
// mode 2: F = (F + y)/2
// mode 3: mode 2 + write dout
__global__ __launch_bounds__(256) void post_kernel(
    const float* __restrict__ bias,
    const float* __restrict__ gam, const float* __restrict__ bet,
    const float* __restrict__ F3, const float* __restrict__ P,
    float* __restrict__ dout, int mode)
{
    int v = blockIdx.x, t = threadIdx.x;
    __shared__ float ybuf[BB * HH];
    __shared__ int   s_nbr[8];
    __shared__ float s_w[8];
    __shared__ int   s_cnt;
    __shared__ float redS[8], redQ[8];
    __shared__ float s_mean, s_istd;

    if (t < 8) { s_nbr[t] = g_nbr[v * 8 + t]; s_w[t] = g_w[v * 8 + t]; }
    if (t == 0) s_cnt = g_cnt[v];
    __syncthreads();
    int cnt = s_cnt;

    float s = 0.f, ss = 0.f;
    #pragma unroll
    for (int it = 0; it < 12; it++) {
        int i = t + it * 256;                 // pair index in [0, 3072)
        int b = i / KP_H, cp = i - b * KP_H;
        int c = 2 * cp;
        float y0, y1;
        if (cp < 64) {
            float2 p = *reinterpret_cast<const float2*>(
                &g_S[((size_t)(b * VV + v)) * HH + c + 64]);
            y0 = p.x; y1 = p.y;
        } else {
            int d = c - 128;
            y0 = 0.f; y1 = 0.f;
            for (int j = 0; j < cnt; j++) {
                float2 p = *reinterpret_cast<const float2*>(
                    &g_S[((size_t)(b * VV + s_nbr[j])) * HH + d]);
                y0 += s_w[j] * p.x; y1 += s_w[j] * p.y;
            }
        }
        y0 += bias[c]; y1 += bias[c + 1];
        ybuf[2 * i] = y0; ybuf[2 * i + 1] = y1;
        s += y0 + y1; ss += y0 * y0 + y1 * y1;
    }
    #pragma unroll
    for (int o = 16; o > 0; o >>= 1) {
        s  += __shfl_down_sync(0xffffffffu, s, o);
        ss += __shfl_down_sync(0xffffffffu, ss, o);
    }
    int lane = t & 31, warp = t >> 5;
    if (lane == 0) { redS[warp] = s; redQ[warp] = ss; }
    __syncthreads();
    if (t == 0) {
        float S = 0.f, Q = 0.f;
        #pragma unroll
        for (int w = 0; w < 8; w++) { S += redS[w]; Q += redQ[w]; }
        float n = (float)(BB * HH);
        float mu = S / n;
        s_mean = mu;
        s_istd = rsqrtf(Q / n - mu * mu + 1e-5f);
    }
    __syncthreads();

    float gv = gam[v], bv = bet[v], mu = s_mean, istd = s_istd;
    #pragma unroll
    for (int it = 0; it < 12; it++) {
        int i = t + it * 256;
        int b = i / KP_H, cp = i - b * KP_H;
        int c = 2 * cp;
        int m = b * VV + v;
        float y0 = fmaxf(gv * (ybuf[2 * i]     - mu) * istd + bv, 0.f);
        float y1 = fmaxf(gv * (ybuf[2 * i + 1] - mu) * istd + bv, 0.f);
        size_t pidx = (size_t)m * KP_H + cp;
        if (mode == 0) {
            split2(y0, y1, g_Xh[pidx], g_Xl[pidx]);
        } else {
            float r0, r1;
            if (mode == 1) {
                float b0 = (c < 3)     ? F3[m * 3 + c]     : P[(size_t)m * 963 + (c - 3)];
                float b1 = (c + 1 < 3) ? F3[m * 3 + c + 1] : P[(size_t)m * 963 + (c - 2)];
                r0 = (b0 + y0) * 0.5f; r1 = (b1 + y1) * 0.5f;
            } else {
                float2 f = *reinterpret_cast<const float2*>(&g_F[(size_t)m * HH + c]);
                r0 = (f.x + y0) * 0.5f; r1 = (f.y + y1) * 0.5f;
            }
            *reinterpret_cast<float2*>(&g_F[(size_t)m * HH + c]) = make_float2(r0, r1);
            split2(r0, r1, g_Fh[pidx], g_Fl[pidx]);
            if (mode == 3)
                *reinterpret_cast<float2*>(&dout[(size_t)m * HH + c]) = make_float2(r0, r1);
        }
    }
}

// ---------------- head GEMM: S3 = feats @ W15, cols<2 pre-scaled -------------
__global__ __launch_bounds__(256) void gemm3_kernel(const float* __restrict__ W15) {
    int warp = (blockIdx.x * blockDim.x + threadIdx.x) >> 5;
    int lane = threadIdx.x & 31;
    if (warp >= MDIM) return;
    const float* row = g_F + (size_t)warp * HH;
    float a0 = 0.f, a1 = 0.f, a2 = 0.f;
    for (int k = lane; k < HH; k += 32) {
        float f = row[k];
        a0 = fmaf(f, W15[k * 3 + 0], a0);
        a1 = fmaf(f, W15[k * 3 + 1], a1);
        a2 = fmaf(f, W15[k * 3 + 2], a2);
    }
    #pragma unroll
    for (int o = 16; o > 0; o >>= 1) {
        a0 += __shfl_down_sync(0xffffffffu, a0, o);
        a1 += __shfl_down_sync(0xffffffffu, a1, o);
        a2 += __shfl_down_sync(0xffffffffu, a2, o);
    }
    if (lane == 0) {
        float inv = g_invdeg[warp % VV];
        g_S3[warp * 3 + 0] = a0 * inv;
        g_S3[warp * 3 + 1] = a1 * inv;
        g_S3[warp * 3 + 2] = a2;
    }
}

__global__ __launch_bounds__(256) void coords_kernel(float* __restrict__ dout,
                                                     const float* __restrict__ b15) {
    int m = blockIdx.x * blockDim.x + threadIdx.x;
    if (m >= MDIM) return;
    int v = m % VV, b = m / VV;
    float s0 = 0.f, s1 = 0.f;
    int cnt = g_cnt[v];
    for (int j = 0; j < cnt; j++) {
        int nv = g_nbr[v * 8 + j];
        float w = g_w[v * 8 + j];
        const float* p = g_S3 + (size_t)(b * VV + nv) * 3;
        s0 += w * p[0];
        s1 += w * p[1];
    }
    float* o = dout + (size_t)MDIM * HH + (size_t)m * 3;
    o[0] = g_S3[m * 3 + 2] + b15[0];
    o[1] = s0 + b15[1];
    o[2] = s1 + b15[2];
}

// ---------------- driver ----------------------------------------------------
extern "C" void kernel_launch(void* const* d_in, const int* in_sizes, int n_in,
                              void* d_out, int out_size) {
    const float* features = (const float*)d_in[0];
    const float* pooled   = (const float*)d_in[1];
    const float* adj      = (const float*)d_in[2];
    const float* W1       = (const float*)d_in[3];
    const float* b1       = (const float*)d_in[4];
    const float* Wm       = (const float*)d_in[5];
    const float* bm       = (const float*)d_in[6];
    const float* W15      = (const float*)d_in[7];
    const float* b15      = (const float*)d_in[8];
    const float* gamma    = (const float*)d_in[9];
    const float* beta     = (const float*)d_in[10];
    float* dout = (float*)d_out;

    dim3 ggrid(3, (MDIM + 127) / 128);

    adj_kernel<<<(VV + 7) / 8, 256>>>(adj);
    prep_w_kernel<<<(WROWS * HH + 255) / 256, 256>>>(W1, Wm);
    prep_a1_kernel<<<(int)(((size_t)MDIM * KP_1 + 255) / 256), 256>>>(features, pooled);

    // layer 1: A = concat planes, W1 at woff 0
    gemm_bf3_kernel<<<ggrid, 256>>>(2, 0, NT_1);
    post_kernel<<<VV, 256>>>(b1, gamma + 0 * VV, beta + 0 * VV, features, pooled, dout, 0);

    // layer 2: A = X, Wm[0]
    gemm_bf3_kernel<<<ggrid, 256>>>(0, KP_1 + 0 * KP_H, NT_H);
    post_kernel<<<VV, 256>>>(bm + 0 * HH, gamma + 1 * VV, beta + 1 * VV, features, pooled, dout, 1);

    for (int i = 0; i < 5; i++) {
        int wa = 2 * i + 1, wb = 2 * i + 2;
        gemm_bf3_kernel<<<ggrid, 256>>>(1, KP_1 + wa * KP_H, NT_H);
        post_kernel<<<VV, 256>>>(bm + wa * HH, gamma + (2 * i + 2) * VV, beta + (2 * i + 2) * VV,
                                 features, pooled, dout, 0);
        gemm_bf3_kernel<<<ggrid, 256>>>(0, KP_1 + wb * KP_H, NT_H);
        post_kernel<<<VV, 256>>>(bm + wb * HH, gamma + (2 * i + 3) * VV, beta + (2 * i + 3) * VV,
                                 features, pooled, dout, 2);
    }

    // layer 13
    gemm_bf3_kernel<<<ggrid, 256>>>(1, KP_1 + 11 * KP_H, NT_H);
    post_kernel<<<VV, 256>>>(bm + 11 * HH, gamma + 12 * VV, beta + 12 * VV, features, pooled, dout, 3);

    gemm3_kernel<<<(MDIM * 32 + 255) / 256, 256>>>(W15);
    coords_kernel<<<(MDIM + 255) / 256, 256>>>(dout, b15);
}

// round 4
// speedup vs baseline: 4.0431x; 1.5057x over previous
#include <cuda_runtime.h>
#include <cuda_fp16.h>
#include <cstdint>

#define MDIM 81984   // B*V
#define VV   2562
#define HH   192
#define BB   32
#define KP_H 96      // k-pairs for K=192
#define KP_1 488     // k-pairs for layer1 (K=966 padded to 976)
#define NT_H 12
#define NT_1 61
#define WROWS (KP_1 + 12 * KP_H)

// ---------------- scratch (device globals) ----------------------------------
static __device__ float    g_S [(size_t)MDIM * HH];     // GEMM out (side pre-scaled)
static __device__ float    g_F [(size_t)MDIM * HH];     // feats fp32
static __device__ uint32_t g_Xp [(size_t)MDIM * KP_H];  // X fp16 pairs (single plane)
static __device__ uint32_t g_Fp [(size_t)MDIM * KP_H];  // feats fp16 pairs
static __device__ uint32_t g_A1p[(size_t)MDIM * KP_1];  // layer1 concat fp16 pairs
static __device__ uint32_t g_Wh [(size_t)WROWS * HH];   // weight hi fp16 pairs [kpair][n]
static __device__ uint32_t g_Wl [(size_t)WROWS * HH];   // weight lo fp16 pairs
static __device__ float    g_S3[(size_t)MDIM * 3];
static __device__ int      g_nbr[VV * 8];
static __device__ float    g_w [VV * 8];
static __device__ int      g_cnt[VV];
static __device__ float    g_invdeg[VV];

// ---------------- helpers ----------------------------------------------------
__device__ __forceinline__ uint32_t packh2(float x0, float x1) {
    __half2 h = __floats2half2_rn(x0, x1);
    return *reinterpret_cast<uint32_t*>(&h);
}

__device__ __forceinline__ void mma16(float* c, const uint32_t* a, const uint32_t* b) {
    asm volatile(
        "mma.sync.aligned.m16n8k16.row.col.f32.f16.f16.f32 "
        "{%0,%1,%2,%3}, {%4,%5,%6,%7}, {%8,%9}, {%0,%1,%2,%3};\n"
        : "+f"(c[0]), "+f"(c[1]), "+f"(c[2]), "+f"(c[3])
        : "r"(a[0]), "r"(a[1]), "r"(a[2]), "r"(a[3]), "r"(b[0]), "r"(b[1]));
}

__device__ __forceinline__ uint32_t smem_u32(const void* p) {
    return (uint32_t)__cvta_generic_to_shared(p);
}
__device__ __forceinline__ void cpa16(uint32_t dst, const void* src, int sz) {
    asm volatile("cp.async.cg.shared.global [%0], [%1], 16, %2;\n"
                 :: "r"(dst), "l"(src), "r"(sz));
}

// ---------------- adjacency extraction ---------------------------------------
__global__ __launch_bounds__(256) void adj_kernel(const float* __restrict__ adj) {
    int u = blockIdx.x * (blockDim.x / 32) + (threadIdx.x / 32);
    int lane = threadIdx.x & 31;
    if (u >= VV) return;
    int cnt = 0;
    float deg = 0.f;
    for (int base = 0; base < VV; base += 32) {
        int v = base + lane;
        float f = (v < VV) ? adj[(size_t)u * VV + v] : 0.f;
        unsigned mask = __ballot_sync(0xffffffffu, f != 0.f);
        deg += f;
        if (f != 0.f) {
            int pos = cnt + __popc(mask & ((1u << lane) - 1u));
            if (pos < 8) { g_nbr[u * 8 + pos] = v; g_w[u * 8 + pos] = f; }
        }
        cnt += __popc(mask);
    }
    #pragma unroll
    for (int o = 16; o > 0; o >>= 1) deg += __shfl_down_sync(0xffffffffu, deg, o);
    if (lane == 0) {
        g_cnt[u] = cnt < 8 ? cnt : 8;
        g_invdeg[u] = 1.f / deg;
    }
}

// ---------------- weight pre-split (fp16 hi/lo): W1 + Wm ---------------------
__global__ __launch_bounds__(256) void prep_w_kernel(const float* __restrict__ W1,
                                                     const float* __restrict__ Wm) {
    int idx = blockIdx.x * 256 + threadIdx.x;
    if (idx >= WROWS * HH) return;
    int kp = idx / HH, n = idx % HH;
    float x0, x1;
    if (kp < KP_1) {
        int k = 2 * kp;
        x0 = (k < 966)     ? W1[(size_t)k * HH + n]       : 0.f;
        x1 = (k + 1 < 966) ? W1[(size_t)(k + 1) * HH + n] : 0.f;
    } else {
        int r = kp - KP_1;
        int mat = r / KP_H, kpp = r % KP_H;
        int k = 2 * kpp;
        const float* Wb = Wm + (size_t)mat * HH * HH;
        x0 = Wb[(size_t)k * HH + n];
        x1 = Wb[(size_t)(k + 1) * HH + n];
    }
    __half h0 = __float2half_rn(x0), h1 = __float2half_rn(x1);
    float r0 = x0 - __half2float(h0), r1 = x1 - __half2float(h1);
    g_Wh[idx] = (uint32_t)__half_as_ushort(h0) | ((uint32_t)__half_as_ushort(h1) << 16);
    g_Wl[idx] = packh2(r0, r1);
}

// ---------------- layer1 input pack: concat(F3,P) -> g_A1p --------------------
__global__ __launch_bounds__(256) void prep_a1_kernel(const float* __restrict__ F3,
                                                      const float* __restrict__ P) {
    size_t idx = (size_t)blockIdx.x * 256 + threadIdx.x;
    if (idx >= (size_t)MDIM * KP_1) return;
    int m = (int)(idx / KP_1), kp = (int)(idx % KP_1);
    int c = 2 * kp;
    float x0 = 0.f, x1 = 0.f;
    if (c < 3)        x0 = F3[m * 3 + c];
    else if (c < 966) x0 = P[(size_t)m * 963 + (c - 3)];
    int c1 = c + 1;
    if (c1 < 3)        x1 = F3[m * 3 + c1];
    else if (c1 < 966) x1 = P[(size_t)m * 963 + (c1 - 3)];
    g_A1p[idx] = packh2(x0, x1);
}

// ---------------- fp16x2 tensor-core GEMM: g_S = A[M,K] @ W[K,192] ------------
// block tile 256x64, warp tile 64x32 (4mt x 4nt), 3-stage cp.async pipeline
// epilogue: cols < 64 scaled by invdeg[row % V]
// asel: 0 -> g_Xp (akp=96), 1 -> g_Fp (96), 2 -> g_A1p (488)
__global__ __launch_bounds__(256, 2) void gemm_f16_kernel(int asel, int woff, int NT) {
    __shared__ uint32_t As[3][256][8];      // swizzled: col ^= ((row>>2)&1)*4
    __shared__ uint32_t Bs[3][2][8][72];    // [stage][plane][kpair][n], padded

    const uint32_t* Ap; int akp;
    if (asel == 0)      { Ap = g_Xp;  akp = KP_H; }
    else if (asel == 1) { Ap = g_Fp;  akp = KP_H; }
    else                { Ap = g_A1p; akp = KP_1; }

    int t = threadIdx.x, lane = t & 31, warp = t >> 5;
    int wm = (warp >> 1) * 64, wn = (warp & 1) * 32;
    int g = lane >> 2, t4 = lane & 3;
    int rowBase = blockIdx.y * 256, colBase = blockIdx.x * 64;

    float acc[4][4][4];
    #pragma unroll
    for (int mt = 0; mt < 4; mt++)
        #pragma unroll
        for (int nt = 0; nt < 4; nt++)
            #pragma unroll
            for (int i = 0; i < 4; i++) acc[mt][nt][i] = 0.f;

    // loader constants
    int b_pl = t >> 7, b_kp = (t >> 4) & 7, b_n4 = (t & 15) * 4;
    const uint32_t* Wp = b_pl ? g_Wl : g_Wh;

    auto load_stage = [&](int kt) {
        int s = kt % 3;
        int k0p = kt * 8;
        int ok = (kt < NT) ? 16 : 0;
        // A: 2x16B per thread
        #pragma unroll
        for (int i = 0; i < 2; i++) {
            int c = t + i * 256;
            int row = c >> 1, half = c & 1;
            int gm = rowBase + row;
            int dcol = (half * 4) ^ (((row >> 2) & 1) * 4);
            cpa16(smem_u32(&As[s][row][dcol]),
                  Ap + (size_t)gm * akp + k0p + half * 4,
                  (gm < MDIM) ? ok : 0);
        }
        // B: 1x16B per thread
        cpa16(smem_u32(&Bs[s][b_pl][b_kp][b_n4]),
              Wp + (size_t)(woff + k0p + b_kp) * HH + colBase + b_n4,
              ok);
        asm volatile("cp.async.commit_group;\n");
    };

    load_stage(0);
    load_stage(1);

    for (int kt = 0; kt < NT; kt++) {
        asm volatile("cp.async.wait_group %0;\n" :: "n"(1));
        __syncthreads();
        load_stage(kt + 2);

        int s = kt % 3;
        uint32_t a[4][4];
        #pragma unroll
        for (int mt = 0; mt < 4; mt++) {
            int rm = wm + mt * 16 + g;
            int sw = ((rm >> 2) & 1) * 4;
            a[mt][0] = As[s][rm][t4 ^ sw];
            a[mt][1] = As[s][rm + 8][t4 ^ sw];
            a[mt][2] = As[s][rm][(t4 + 4) ^ sw];
            a[mt][3] = As[s][rm + 8][(t4 + 4) ^ sw];
        }
        #pragma unroll
        for (int nt = 0; nt < 4; nt++) {
            int cn = wn + nt * 8 + g;
            uint32_t bh[2] = { Bs[s][0][t4][cn], Bs[s][0][t4 + 4][cn] };
            uint32_t bl[2] = { Bs[s][1][t4][cn], Bs[s][1][t4 + 4][cn] };
            #pragma unroll
            for (int mt = 0; mt < 4; mt++) {
                mma16(acc[mt][nt], a[mt], bh);
                mma16(acc[mt][nt], a[mt], bl);
            }
        }
    }

    // ---- epilogue ----
    #pragma unroll
    for (int mt = 0; mt < 4; mt++) {
        int gm0 = rowBase + wm + mt * 16 + g;
        #pragma unroll
        for (int nt = 0; nt < 4; nt++) {
            int gc = colBase + wn + nt * 8 + t4 * 2;
            bool side = (gc < 64);
            if (gm0 < MDIM) {
                float sc = side ? g_invdeg[gm0 % VV] : 1.f;
                *reinterpret_cast<float2*>(&g_S[(size_t)gm0 * HH + gc]) =
                    make_float2(acc[mt][nt][0] * sc, acc[mt][nt][1] * sc);
            }
            int gm1 = gm0 + 8;
            if (gm1 < MDIM) {
                float sc = side ? g_invdeg[gm1 % VV] : 1.f;
                *reinterpret_cast<float2*>(&g_S[(size_t)gm1 * HH + gc]) =
                    make_float2(acc[mt][nt][2] * sc, acc[mt][nt][3] * sc);
            }
        }
    }
}

// ---------------- fused combine + BN stats + apply (per vertex) --------------
// mode 0: X = relu(bn)                (write g_Xp plane)
// mode 1: F = (concat_first192+y)/2   (write g_F + g_Fp)
// mode 2: F = (F + y)/2
// mode 3: mode 2 + write dout
__global__ __launch_bounds__(256) void post_kernel(
    const float* __restrict__ bias,
    const float* __restrict__ gam, const float* __restrict__ bet,
    const float* __restrict__ F3, const float* __restrict__ P,
    float* __restrict__ dout, int mode)
{
    int v = blockIdx.x, t = threadIdx.x;
    __shared__ float ybuf[BB * HH];
    __shared__ int   s_nbr[8];
    __shared__ float s_w[8];
    __shared__ int   s_cnt;
    __shared__ float redS[8], redQ[8];
    __shared__ float s_mean, s_istd;

    if (t < 8) { s_nbr[t] = g_nbr[v * 8 + t]; s_w[t] = g_w[v * 8 + t]; }
    if (t == 0) s_cnt = g_cnt[v];
    __syncthreads();
    int cnt = s_cnt;

    float s = 0.f, ss = 0.f;
    #pragma unroll
    for (int it = 0; it < 12; it++) {
        int i = t + it * 256;
        int b = i / KP_H, cp = i - b * KP_H;
        int c = 2 * cp;
        float y0, y1;
        if (cp < 64) {
            float2 p = *reinterpret_cast<const float2*>(
                &g_S[((size_t)(b * VV + v)) * HH + c + 64]);
            y0 = p.x; y1 = p.y;
        } else {
            int d = c - 128;
            y0 = 0.f; y1 = 0.f;
            for (int j = 0; j < cnt; j++) {
                float2 p = *reinterpret_cast<const float2*>(
                    &g_S[((size_t)(b * VV + s_nbr[j])) * HH + d]);
                y0 += s_w[j] * p.x; y1 += s_w[j] * p.y;
            }
        }
        y0 += bias[c]; y1 += bias[c + 1];
        ybuf[2 * i] = y0; ybuf[2 * i + 1] = y1;
        s += y0 + y1; ss += y0 * y0 + y1 * y1;
    }
    #pragma unroll
    for (int o = 16; o > 0; o >>= 1) {
        s  += __shfl_down_sync(0xffffffffu, s, o);
        ss += __shfl_down_sync(0xffffffffu, ss, o);
    }
    int lane = t & 31, warp = t >> 5;
    if (lane == 0) { redS[warp] = s; redQ[warp] = ss; }
    __syncthreads();
    if (t == 0) {
        float S = 0.f, Q = 0.f;
        #pragma unroll
        for (int w = 0; w < 8; w++) { S += redS[w]; Q += redQ[w]; }
        float n = (float)(BB * HH);
        float mu = S / n;
        s_mean = mu;
        s_istd = rsqrtf(Q / n - mu * mu + 1e-5f);
    }
    __syncthreads();

    float gv = gam[v], bv = bet[v], mu = s_mean, istd = s_istd;
    #pragma unroll
    for (int it = 0; it < 12; it++) {
        int i = t + it * 256;
        int b = i / KP_H, cp = i - b * KP_H;
        int c = 2 * cp;
        int m = b * VV + v;
        float y0 = fmaxf(gv * (ybuf[2 * i]     - mu) * istd + bv, 0.f);
        float y1 = fmaxf(gv * (ybuf[2 * i + 1] - mu) * istd + bv, 0.f);
        size_t pidx = (size_t)m * KP_H + cp;
        if (mode == 0) {
            g_Xp[pidx] = packh2(y0, y1);
        } else {
            float r0, r1;
            if (mode == 1) {
                float b0 = (c < 3)     ? F3[m * 3 + c]     : P[(size_t)m * 963 + (c - 3)];
                float b1 = (c + 1 < 3) ? F3[m * 3 + c + 1] : P[(size_t)m * 963 + (c - 2)];
                r0 = (b0 + y0) * 0.5f; r1 = (b1 + y1) * 0.5f;
            } else {
                float2 f = *reinterpret_cast<const float2*>(&g_F[(size_t)m * HH + c]);
                r0 = (f.x + y0) * 0.5f; r1 = (f.y + y1) * 0.5f;
            }
            *reinterpret_cast<float2*>(&g_F[(size_t)m * HH + c]) = make_float2(r0, r1);
            g_Fp[pidx] = packh2(r0, r1);
            if (mode == 3)
                *reinterpret_cast<float2*>(&dout[(size_t)m * HH + c]) = make_float2(r0, r1);
        }
    }
}

// ---------------- head GEMM: S3 = feats @ W15, cols<2 pre-scaled -------------
__global__ __launch_bounds__(256) void gemm3_kernel(const float* __restrict__ W15) {
    int warp = (blockIdx.x * blockDim.x + threadIdx.x) >> 5;
    int lane = threadIdx.x & 31;
    if (warp >= MDIM) return;
    const float* row = g_F + (size_t)warp * HH;
    float a0 = 0.f, a1 = 0.f, a2 = 0.f;
    for (int k = lane; k < HH; k += 32) {
        float f = row[k];
        a0 = fmaf(f, W15[k * 3 + 0], a0);
        a1 = fmaf(f, W15[k * 3 + 1], a1);
        a2 = fmaf(f, W15[k * 3 + 2], a2);
    }
    #pragma unroll
    for (int o = 16; o > 0; o >>= 1) {
        a0 += __shfl_down_sync(0xffffffffu, a0, o);
        a1 += __shfl_down_sync(0xffffffffu, a1, o);
        a2 += __shfl_down_sync(0xffffffffu, a2, o);
    }
    if (lane == 0) {
        float inv = g_invdeg[warp % VV];
        g_S3[warp * 3 + 0] = a0 * inv;
        g_S3[warp * 3 + 1] = a1 * inv;
        g_S3[warp * 3 + 2] = a2;
    }
}

__global__ __launch_bounds__(256) void coords_kernel(float* __restrict__ dout,
                                                     const float* __restrict__ b15) {
    int m = blockIdx.x * blockDim.x + threadIdx.x;
    if (m >= MDIM) return;
    int v = m % VV, b = m / VV;
    float s0 = 0.f, s1 = 0.f;
    int cnt = g_cnt[v];
    for (int j = 0; j < cnt; j++) {
        int nv = g_nbr[v * 8 + j];
        float w = g_w[v * 8 + j];
        const float* p = g_S3 + (size_t)(b * VV + nv) * 3;
        s0 += w * p[0];
        s1 += w * p[1];
    }
    float* o = dout + (size_t)MDIM * HH + (size_t)m * 3;
    o[0] = g_S3[m * 3 + 2] + b15[0];
    o[1] = s0 + b15[1];
    o[2] = s1 + b15[2];
}

// ---------------- driver ----------------------------------------------------
extern "C" void kernel_launch(void* const* d_in, const int* in_sizes, int n_in,
                              void* d_out, int out_size) {
    const float* features = (const float*)d_in[0];
    const float* pooled   = (const float*)d_in[1];
    const float* adj      = (const float*)d_in[2];
    const float* W1       = (const float*)d_in[3];
    const float* b1       = (const float*)d_in[4];
    const float* Wm       = (const float*)d_in[5];
    const float* bm       = (const float*)d_in[6];
    const float* W15      = (const float*)d_in[7];
    const float* b15      = (const float*)d_in[8];
    const float* gamma    = (const float*)d_in[9];
    const float* beta     = (const float*)d_in[10];
    float* dout = (float*)d_out;

    dim3 ggrid(3, (MDIM + 255) / 256);

    adj_kernel<<<(VV + 7) / 8, 256>>>(adj);
    prep_w_kernel<<<(WROWS * HH + 255) / 256, 256>>>(W1, Wm);
    prep_a1_kernel<<<(int)(((size_t)MDIM * KP_1 + 255) / 256), 256>>>(features, pooled);

    // layer 1
    gemm_f16_kernel<<<ggrid, 256>>>(2, 0, NT_1);
    post_kernel<<<VV, 256>>>(b1, gamma + 0 * VV, beta + 0 * VV, features, pooled, dout, 0);

    // layer 2
    gemm_f16_kernel<<<ggrid, 256>>>(0, KP_1 + 0 * KP_H, NT_H);
    post_kernel<<<VV, 256>>>(bm + 0 * HH, gamma + 1 * VV, beta + 1 * VV, features, pooled, dout, 1);

    for (int i = 0; i < 5; i++) {
        int wa = 2 * i + 1, wb = 2 * i + 2;
        gemm_f16_kernel<<<ggrid, 256>>>(1, KP_1 + wa * KP_H, NT_H);
        post_kernel<<<VV, 256>>>(bm + wa * HH, gamma + (2 * i + 2) * VV, beta + (2 * i + 2) * VV,
                                 features, pooled, dout, 0);
        gemm_f16_kernel<<<ggrid, 256>>>(0, KP_1 + wb * KP_H, NT_H);
        post_kernel<<<VV, 256>>>(bm + wb * HH, gamma + (2 * i + 3) * VV, beta + (2 * i + 3) * VV,
                                 features, pooled, dout, 2);
    }

    // layer 13
    gemm_f16_kernel<<<ggrid, 256>>>(1, KP_1 + 11 * KP_H, NT_H);
    post_kernel<<<VV, 256>>>(bm + 11 * HH, gamma + 12 * VV, beta + 12 * VV, features, pooled, dout, 3);

    gemm3_kernel<<<(MDIM * 32 + 255) / 256, 256>>>(W15);
    coords_kernel<<<(MDIM + 255) / 256, 256>>>(dout, b15);
}

// round 5
// speedup vs baseline: 4.5403x; 1.1230x over previous
#include <cuda_runtime.h>
#include <cuda_fp16.h>
#include <cstdint>

#define MDIM 81984   // B*V
#define VV   2562
#define HH   192
#define BB   32
#define KP_H 96      // k-pairs for K=192
#define KP_1 488     // k-pairs for layer1 (K=966 padded to 976)
#define NT_H 12
#define NT_1 61
#define WROWS (KP_1 + 12 * KP_H)

// ---------------- scratch (device globals) ----------------------------------
static __device__ uint32_t g_Sp[(size_t)MDIM * KP_H];   // GEMM out, half2 pairs (side pre-scaled)
static __device__ float    g_F [(size_t)MDIM * HH];     // feats fp32
static __device__ uint32_t g_Xp [(size_t)MDIM * KP_H];  // X fp16 pairs
static __device__ uint32_t g_Fp [(size_t)MDIM * KP_H];  // feats fp16 pairs
static __device__ uint32_t g_A1p[(size_t)MDIM * KP_1];  // layer1 concat fp16 pairs
static __device__ uint32_t g_W  [(size_t)WROWS * HH];   // weight fp16 pairs [kpair][n]
static __device__ float    g_S3[(size_t)MDIM * 3];
static __device__ int      g_nbr[VV * 8];
static __device__ float    g_w [VV * 8];
static __device__ int      g_cnt[VV];
static __device__ float    g_invdeg[VV];

// ---------------- helpers ----------------------------------------------------
__device__ __forceinline__ uint32_t packh2(float x0, float x1) {
    __half2 h = __floats2half2_rn(x0, x1);
    return *reinterpret_cast<uint32_t*>(&h);
}
__device__ __forceinline__ float2 unpackh2(uint32_t u) {
    __half2 h = *reinterpret_cast<__half2*>(&u);
    return __half22float2(h);
}

__device__ __forceinline__ void mma16(float* c, const uint32_t* a, const uint32_t* b) {
    asm volatile(
        "mma.sync.aligned.m16n8k16.row.col.f32.f16.f16.f32 "
        "{%0,%1,%2,%3}, {%4,%5,%6,%7}, {%8,%9}, {%0,%1,%2,%3};\n"
        : "+f"(c[0]), "+f"(c[1]), "+f"(c[2]), "+f"(c[3])
        : "r"(a[0]), "r"(a[1]), "r"(a[2]), "r"(a[3]), "r"(b[0]), "r"(b[1]));
}

__device__ __forceinline__ uint32_t smem_u32(const void* p) {
    return (uint32_t)__cvta_generic_to_shared(p);
}
__device__ __forceinline__ void cpa16(uint32_t dst, const void* src, int sz) {
    asm volatile("cp.async.cg.shared.global [%0], [%1], 16, %2;\n"
                 :: "r"(dst), "l"(src), "r"(sz));
}

// ---------------- adjacency extraction ---------------------------------------
__global__ __launch_bounds__(256) void adj_kernel(const float* __restrict__ adj) {
    int u = blockIdx.x * (blockDim.x / 32) + (threadIdx.x / 32);
    int lane = threadIdx.x & 31;
    if (u >= VV) return;
    int cnt = 0;
    float deg = 0.f;
    for (int base = 0; base < VV; base += 32) {
        int v = base + lane;
        float f = (v < VV) ? adj[(size_t)u * VV + v] : 0.f;
        unsigned mask = __ballot_sync(0xffffffffu, f != 0.f);
        deg += f;
        if (f != 0.f) {
            int pos = cnt + __popc(mask & ((1u << lane) - 1u));
            if (pos < 8) { g_nbr[u * 8 + pos] = v; g_w[u * 8 + pos] = f; }
        }
        cnt += __popc(mask);
    }
    #pragma unroll
    for (int o = 16; o > 0; o >>= 1) deg += __shfl_down_sync(0xffffffffu, deg, o);
    if (lane == 0) {
        g_cnt[u] = cnt < 8 ? cnt : 8;
        g_invdeg[u] = 1.f / deg;
    }
}

// ---------------- weight pack (single fp16 plane): W1 + Wm -------------------
__global__ __launch_bounds__(256) void prep_w_kernel(const float* __restrict__ W1,
                                                     const float* __restrict__ Wm) {
    int idx = blockIdx.x * 256 + threadIdx.x;
    if (idx >= WROWS * HH) return;
    int kp = idx / HH, n = idx % HH;
    float x0, x1;
    if (kp < KP_1) {
        int k = 2 * kp;
        x0 = (k < 966)     ? W1[(size_t)k * HH + n]       : 0.f;
        x1 = (k + 1 < 966) ? W1[(size_t)(k + 1) * HH + n] : 0.f;
    } else {
        int r = kp - KP_1;
        int mat = r / KP_H, kpp = r % KP_H;
        int k = 2 * kpp;
        const float* Wb = Wm + (size_t)mat * HH * HH;
        x0 = Wb[(size_t)k * HH + n];
        x1 = Wb[(size_t)(k + 1) * HH + n];
    }
    g_W[idx] = packh2(x0, x1);
}

// ---------------- layer1 input pack: concat(F3,P) -> g_A1p --------------------
__global__ __launch_bounds__(256) void prep_a1_kernel(const float* __restrict__ F3,
                                                      const float* __restrict__ P) {
    size_t idx = (size_t)blockIdx.x * 256 + threadIdx.x;
    if (idx >= (size_t)MDIM * KP_1) return;
    int m = (int)(idx / KP_1), kp = (int)(idx % KP_1);
    int c = 2 * kp;
    float x0 = 0.f, x1 = 0.f;
    if (c < 3)        x0 = F3[m * 3 + c];
    else if (c < 966) x0 = P[(size_t)m * 963 + (c - 3)];
    int c1 = c + 1;
    if (c1 < 3)        x1 = F3[m * 3 + c1];
    else if (c1 < 966) x1 = P[(size_t)m * 963 + (c1 - 3)];
    g_A1p[idx] = packh2(x0, x1);
}

// ---------------- fp16 tensor-core GEMM: g_Sp = A[M,K] @ W[K,192] -------------
// block tile 256x64, warp tile 64x32 (4mt x 4nt), 3-stage cp.async pipeline
// epilogue: cols < 64 scaled by invdeg[row % V]; packed half2 output
// asel: 0 -> g_Xp (akp=96), 1 -> g_Fp (96), 2 -> g_A1p (488)
__global__ __launch_bounds__(256, 2) void gemm_f16_kernel(int asel, int woff, int NT) {
    __shared__ uint32_t As[3][256][8];      // swizzled: col ^= ((row>>2)&1)*4
    __shared__ uint32_t Bs[3][8][72];       // [stage][kpair][n], padded

    const uint32_t* Ap; int akp;
    if (asel == 0)      { Ap = g_Xp;  akp = KP_H; }
    else if (asel == 1) { Ap = g_Fp;  akp = KP_H; }
    else                { Ap = g_A1p; akp = KP_1; }

    int t = threadIdx.x, lane = t & 31, warp = t >> 5;
    int wm = (warp >> 1) * 64, wn = (warp & 1) * 32;
    int g = lane >> 2, t4 = lane & 3;
    int rowBase = blockIdx.y * 256, colBase = blockIdx.x * 64;

    float acc[4][4][4];
    #pragma unroll
    for (int mt = 0; mt < 4; mt++)
        #pragma unroll
        for (int nt = 0; nt < 4; nt++)
            #pragma unroll
            for (int i = 0; i < 4; i++) acc[mt][nt][i] = 0.f;

    // B loader: threads 0-127, one 16B each
    int b_kp = t >> 4, b_n4 = (t & 15) * 4;

    auto load_stage = [&](int kt) {
        int s = kt % 3;
        int k0p = kt * 8;
        int ok = (kt < NT) ? 16 : 0;
        #pragma unroll
        for (int i = 0; i < 2; i++) {
            int c = t + i * 256;
            int row = c >> 1, half = c & 1;
            int gm = rowBase + row;
            int dcol = (half * 4) ^ (((row >> 2) & 1) * 4);
            cpa16(smem_u32(&As[s][row][dcol]),
                  Ap + (size_t)gm * akp + k0p + half * 4,
                  (gm < MDIM) ? ok : 0);
        }
        if (t < 128)
            cpa16(smem_u32(&Bs[s][b_kp][b_n4]),
                  g_W + (size_t)(woff + k0p + b_kp) * HH + colBase + b_n4,
                  ok);
        asm volatile("cp.async.commit_group;\n");
    };

    load_stage(0);
    load_stage(1);

    for (int kt = 0; kt < NT; kt++) {
        asm volatile("cp.async.wait_group %0;\n" :: "n"(1));
        __syncthreads();
        load_stage(kt + 2);

        int s = kt % 3;
        uint32_t a[4][4];
        #pragma unroll
        for (int mt = 0; mt < 4; mt++) {
            int rm = wm + mt * 16 + g;
            int sw = ((rm >> 2) & 1) * 4;
            a[mt][0] = As[s][rm][t4 ^ sw];
            a[mt][1] = As[s][rm + 8][t4 ^ sw];
            a[mt][2] = As[s][rm][(t4 + 4) ^ sw];
            a[mt][3] = As[s][rm + 8][(t4 + 4) ^ sw];
        }
        #pragma unroll
        for (int nt = 0; nt < 4; nt++) {
            int cn = wn + nt * 8 + g;
            uint32_t b[2] = { Bs[s][t4][cn], Bs[s][t4 + 4][cn] };
            #pragma unroll
            for (int mt = 0; mt < 4; mt++)
                mma16(acc[mt][nt], a[mt], b);
        }
    }

    // ---- epilogue: pack half2, scale side channels ----
    #pragma unroll
    for (int mt = 0; mt < 4; mt++) {
        int gm0 = rowBase + wm + mt * 16 + g;
        #pragma unroll
        for (int nt = 0; nt < 4; nt++) {
            int gc = colBase + wn + nt * 8 + t4 * 2;
            int cp = gc >> 1;
            bool side = (gc < 64);
            if (gm0 < MDIM) {
                float sc = side ? g_invdeg[gm0 % VV] : 1.f;
                g_Sp[(size_t)gm0 * KP_H + cp] = packh2(acc[mt][nt][0] * sc, acc[mt][nt][1] * sc);
            }
            int gm1 = gm0 + 8;
            if (gm1 < MDIM) {
                float sc = side ? g_invdeg[gm1 % VV] : 1.f;
                g_Sp[(size_t)gm1 * KP_H + cp] = packh2(acc[mt][nt][2] * sc, acc[mt][nt][3] * sc);
            }
        }
    }
}

// ---------------- fused combine + BN stats + apply (per vertex) --------------
// mode 0: X = relu(bn)                (write g_Xp plane)
// mode 1: F = (concat_first192+y)/2   (write g_F + g_Fp)
// mode 2: F = (F + y)/2
// mode 3: mode 2 + write dout
__global__ __launch_bounds__(256) void post_kernel(
    const float* __restrict__ bias,
    const float* __restrict__ gam, const float* __restrict__ bet,
    const float* __restrict__ F3, const float* __restrict__ P,
    float* __restrict__ dout, int mode)
{
    int v = blockIdx.x, t = threadIdx.x;
    __shared__ float ybuf[BB * HH];
    __shared__ int   s_nbr[8];
    __shared__ float s_w[8];
    __shared__ int   s_cnt;
    __shared__ float redS[8], redQ[8];
    __shared__ float s_mean, s_istd;

    if (t < 8) { s_nbr[t] = g_nbr[v * 8 + t]; s_w[t] = g_w[v * 8 + t]; }
    if (t == 0) s_cnt = g_cnt[v];
    __syncthreads();
    int cnt = s_cnt;

    float s = 0.f, ss = 0.f;
    #pragma unroll
    for (int it = 0; it < 12; it++) {
        int i = t + it * 256;
        int b = i / KP_H, cp = i - b * KP_H;
        int c = 2 * cp;
        float y0, y1;
        if (cp < 64) {
            float2 p = unpackh2(g_Sp[((size_t)(b * VV + v)) * KP_H + cp + 32]);
            y0 = p.x; y1 = p.y;
        } else {
            int dp = cp - 64;
            y0 = 0.f; y1 = 0.f;
            for (int j = 0; j < cnt; j++) {
                float2 p = unpackh2(g_Sp[((size_t)(b * VV + s_nbr[j])) * KP_H + dp]);
                y0 += s_w[j] * p.x; y1 += s_w[j] * p.y;
            }
        }
        y0 += bias[c]; y1 += bias[c + 1];
        ybuf[2 * i] = y0; ybuf[2 * i + 1] = y1;
        s += y0 + y1; ss += y0 * y0 + y1 * y1;
    }
    #pragma unroll
    for (int o = 16; o > 0; o >>= 1) {
        s  += __shfl_down_sync(0xffffffffu, s, o);
        ss += __shfl_down_sync(0xffffffffu, ss, o);
    }
    int lane = t & 31, warp = t >> 5;
    if (lane == 0) { redS[warp] = s; redQ[warp] = ss; }
    __syncthreads();
    if (t == 0) {
        float S = 0.f, Q = 0.f;
        #pragma unroll
        for (int w = 0; w < 8; w++) { S += redS[w]; Q += redQ[w]; }
        float n = (float)(BB * HH);
        float mu = S / n;
        s_mean = mu;
        s_istd = rsqrtf(Q / n - mu * mu + 1e-5f);
    }
    __syncthreads();

    float gv = gam[v], bv = bet[v], mu = s_mean, istd = s_istd;
    #pragma unroll
    for (int it = 0; it < 12; it++) {
        int i = t + it * 256;
        int b = i / KP_H, cp = i - b * KP_H;
        int c = 2 * cp;
        int m = b * VV + v;
        float y0 = fmaxf(gv * (ybuf[2 * i]     - mu) * istd + bv, 0.f);
        float y1 = fmaxf(gv * (ybuf[2 * i + 1] - mu) * istd + bv, 0.f);
        size_t pidx = (size_t)m * KP_H + cp;
        if (mode == 0) {
            g_Xp[pidx] = packh2(y0, y1);
        } else {
            float r0, r1;
            if (mode == 1) {
                float b0 = (c < 3)     ? F3[m * 3 + c]     : P[(size_t)m * 963 + (c - 3)];
                float b1 = (c + 1 < 3) ? F3[m * 3 + c + 1] : P[(size_t)m * 963 + (c - 2)];
                r0 = (b0 + y0) * 0.5f; r1 = (b1 + y1) * 0.5f;
            } else {
                float2 f = *reinterpret_cast<const float2*>(&g_F[(size_t)m * HH + c]);
                r0 = (f.x + y0) * 0.5f; r1 = (f.y + y1) * 0.5f;
            }
            *reinterpret_cast<float2*>(&g_F[(size_t)m * HH + c]) = make_float2(r0, r1);
            g_Fp[pidx] = packh2(r0, r1);
            if (mode == 3)
                *reinterpret_cast<float2*>(&dout[(size_t)m * HH + c]) = make_float2(r0, r1);
        }
    }
}

// ---------------- head GEMM: S3 = feats @ W15, cols<2 pre-scaled -------------
__global__ __launch_bounds__(256) void gemm3_kernel(const float* __restrict__ W15) {
    int warp = (blockIdx.x * blockDim.x + threadIdx.x) >> 5;
    int lane = threadIdx.x & 31;
    if (warp >= MDIM) return;
    const float* row = g_F + (size_t)warp * HH;
    float a0 = 0.f, a1 = 0.f, a2 = 0.f;
    for (int k = lane; k < HH; k += 32) {
        float f = row[k];
        a0 = fmaf(f, W15[k * 3 + 0], a0);
        a1 = fmaf(f, W15[k * 3 + 1], a1);
        a2 = fmaf(f, W15[k * 3 + 2], a2);
    }
    #pragma unroll
    for (int o = 16; o > 0; o >>= 1) {
        a0 += __shfl_down_sync(0xffffffffu, a0, o);
        a1 += __shfl_down_sync(0xffffffffu, a1, o);
        a2 += __shfl_down_sync(0xffffffffu, a2, o);
    }
    if (lane == 0) {
        float inv = g_invdeg[warp % VV];
        g_S3[warp * 3 + 0] = a0 * inv;
        g_S3[warp * 3 + 1] = a1 * inv;
        g_S3[warp * 3 + 2] = a2;
    }
}

__global__ __launch_bounds__(256) void coords_kernel(float* __restrict__ dout,
                                                     const float* __restrict__ b15) {
    int m = blockIdx.x * blockDim.x + threadIdx.x;
    if (m >= MDIM) return;
    int v = m % VV, b = m / VV;
    float s0 = 0.f, s1 = 0.f;
    int cnt = g_cnt[v];
    for (int j = 0; j < cnt; j++) {
        int nv = g_nbr[v * 8 + j];
        float w = g_w[v * 8 + j];
        const float* p = g_S3 + (size_t)(b * VV + nv) * 3;
        s0 += w * p[0];
        s1 += w * p[1];
    }
    float* o = dout + (size_t)MDIM * HH + (size_t)m * 3;
    o[0] = g_S3[m * 3 + 2] + b15[0];
    o[1] = s0 + b15[1];
    o[2] = s1 + b15[2];
}

// ---------------- driver ----------------------------------------------------
extern "C" void kernel_launch(void* const* d_in, const int* in_sizes, int n_in,
                              void* d_out, int out_size) {
    const float* features = (const float*)d_in[0];
    const float* pooled   = (const float*)d_in[1];
    const float* adj      = (const float*)d_in[2];
    const float* W1       = (const float*)d_in[3];
    const float* b1       = (const float*)d_in[4];
    const float* Wm       = (const float*)d_in[5];
    const float* bm       = (const float*)d_in[6];
    const float* W15      = (const float*)d_in[7];
    const float* b15      = (const float*)d_in[8];
    const float* gamma    = (const float*)d_in[9];
    const float* beta     = (const float*)d_in[10];
    float* dout = (float*)d_out;

    dim3 ggrid(3, (MDIM + 255) / 256);

    adj_kernel<<<(VV + 7) / 8, 256>>>(adj);
    prep_w_kernel<<<(WROWS * HH + 255) / 256, 256>>>(W1, Wm);
    prep_a1_kernel<<<(int)(((size_t)MDIM * KP_1 + 255) / 256), 256>>>(features, pooled);

    // layer 1
    gemm_f16_kernel<<<ggrid, 256>>>(2, 0, NT_1);
    post_kernel<<<VV, 256>>>(b1, gamma + 0 * VV, beta + 0 * VV, features, pooled, dout, 0);

    // layer 2
    gemm_f16_kernel<<<ggrid, 256>>>(0, KP_1 + 0 * KP_H, NT_H);
    post_kernel<<<VV, 256>>>(bm + 0 * HH, gamma + 1 * VV, beta + 1 * VV, features, pooled, dout, 1);

    for (int i = 0; i < 5; i++) {
        int wa = 2 * i + 1, wb = 2 * i + 2;
        gemm_f16_kernel<<<ggrid, 256>>>(1, KP_1 + wa * KP_H, NT_H);
        post_kernel<<<VV, 256>>>(bm + wa * HH, gamma + (2 * i + 2) * VV, beta + (2 * i + 2) * VV,
                                 features, pooled, dout, 0);
        gemm_f16_kernel<<<ggrid, 256>>>(0, KP_1 + wb * KP_H, NT_H);
        post_kernel<<<VV, 256>>>(bm + wb * HH, gamma + (2 * i + 3) * VV, beta + (2 * i + 3) * VV,
                                 features, pooled, dout, 2);
    }

    // layer 13
    gemm_f16_kernel<<<ggrid, 256>>>(1, KP_1 + 11 * KP_H, NT_H);
    post_kernel<<<VV, 256>>>(bm + 11 * HH, gamma + 12 * VV, beta + 12 * VV, features, pooled, dout, 3);

    gemm3_kernel<<<(MDIM * 32 + 255) / 256, 256>>>(W15);
    coords_kernel<<<(MDIM + 255) / 256, 256>>>(dout, b15);
}